// round 9
// baseline (speedup 1.0000x reference)
#include <cuda_runtime.h>
#include <cuda_bf16.h>
#include <cstdint>

#define N 4096
#define DF 64

// Scratch (allocation-free rule: __device__ globals)
__device__ float g_D[(size_t)N * N];   // 64 MB distance matrix, diagonal = +inf
__device__ float g_sq[N];              // squared norms

__device__ __forceinline__ float finf() { return __int_as_float(0x7f800000); }

// ---------------------------------------------------------------------------
// Kernel 0: squared norms
// ---------------------------------------------------------------------------
__global__ void sq_kernel(const float* __restrict__ x) {
    int i = blockIdx.x * blockDim.x + threadIdx.x;
    if (i >= N) return;
    const float4* xi = (const float4*)(x + (size_t)i * DF);
    float s = 0.f;
#pragma unroll
    for (int k = 0; k < DF / 4; k++) {
        float4 v = xi[k];
        s += v.x * v.x + v.y * v.y + v.z * v.z + v.w * v.w;
    }
    g_sq[i] = s;
}

// ---------------------------------------------------------------------------
// Kernel 1: distance matrix, 64x64 tiles, 256 threads, 4x4 per thread.
// ---------------------------------------------------------------------------
__global__ __launch_bounds__(256) void dist_kernel(const float* __restrict__ x) {
    __shared__ __align__(16) float sA[DF * 68];
    __shared__ __align__(16) float sB[DF * 68];

    const int t    = threadIdx.x;
    const int lrow = t >> 2;      // 0..63
    const int q    = t & 3;       // 0..3
    const int i0   = blockIdx.y * 64;
    const int j0   = blockIdx.x * 64;

    {
        const float4* xa = (const float4*)(x + (size_t)(i0 + lrow) * DF) + q * 4;
        const float4* xb = (const float4*)(x + (size_t)(j0 + lrow) * DF) + q * 4;
#pragma unroll
        for (int u = 0; u < 4; u++) {
            float4 va = xa[u];
            float4 vb = xb[u];
            int k0 = q * 16 + u * 4;
            sA[(k0 + 0) * 68 + lrow] = va.x;
            sA[(k0 + 1) * 68 + lrow] = va.y;
            sA[(k0 + 2) * 68 + lrow] = va.z;
            sA[(k0 + 3) * 68 + lrow] = va.w;
            sB[(k0 + 0) * 68 + lrow] = vb.x;
            sB[(k0 + 1) * 68 + lrow] = vb.y;
            sB[(k0 + 2) * 68 + lrow] = vb.z;
            sB[(k0 + 3) * 68 + lrow] = vb.w;
        }
    }
    __syncthreads();

    const int tx = t & 15;
    const int ty = t >> 4;

    float acc[4][4];
#pragma unroll
    for (int r = 0; r < 4; r++)
#pragma unroll
        for (int c = 0; c < 4; c++) acc[r][c] = 0.f;

#pragma unroll 8
    for (int k = 0; k < DF; k++) {
        float4 a = *(const float4*)&sA[k * 68 + ty * 4];
        float4 b = *(const float4*)&sB[k * 68 + tx * 4];
        float av[4] = {a.x, a.y, a.z, a.w};
        float bv[4] = {b.x, b.y, b.z, b.w};
#pragma unroll
        for (int r = 0; r < 4; r++)
#pragma unroll
            for (int c = 0; c < 4; c++) acc[r][c] = fmaf(av[r], bv[c], acc[r][c]);
    }

    float sqI[4], sqJ[4];
#pragma unroll
    for (int r = 0; r < 4; r++) sqI[r] = g_sq[i0 + ty * 4 + r];
#pragma unroll
    for (int c = 0; c < 4; c++) sqJ[c] = g_sq[j0 + tx * 4 + c];

#pragma unroll
    for (int r = 0; r < 4; r++) {
        int gi = i0 + ty * 4 + r;
        float4 o;
        float ov[4];
#pragma unroll
        for (int c = 0; c < 4; c++) {
            int gj = j0 + tx * 4 + c;
            float d2 = sqI[r] + sqJ[c] - 2.f * acc[r][c];
            float d  = sqrtf(fmaxf(d2, 1e-12f));
            ov[c] = (gi == gj) ? finf() : d;
        }
        o.x = ov[0]; o.y = ov[1]; o.z = ov[2]; o.w = ov[3];
        *(float4*)(g_D + (size_t)gi * N + j0 + tx * 4) = o;
    }
}

// ---------------------------------------------------------------------------
// Kernel 2: Prim scan. 256 threads (8 warps), 16 elems/thread.
//
// Warp-cached mind key (Kv,Ki): warp's argmin over its mind slice excluding
// the tree, replicated in every lane. Per step the critical path reduces the
// INCOMING ROW ONLY (mask | tree | pre-min with K | REDUX); the merged-mind
// argmin emerges from min(K, rowmin) by distributivity — exact, incl.
// first-occurrence ties (packed (value,idx) ordering).
//
// Cache maintenance (all off the critical path):
//  - K' = warp REDUX result itself (min(K, rowmin)) — free.
//  - m[] merged via FMNMX interleaved with the tree (fma vs alu pipe).
//  - if K'.idx == winner, that one warp rebuilds K from m[] at the next
//    loop top, hidden under the row-load stall.
//  - msent[e] = 0xFFFFFFFF once in-tree (OR-mask -> sorts after +inf);
//    m[e] = -1.0f sentinel (survives fminf; sorts last as unsigned bits).
//  - output STG and bookkeeping deferred until after the next LDG issues.
// ---------------------------------------------------------------------------
__global__ __launch_bounds__(256, 1) void prim_kernel(float* __restrict__ out) {
    __shared__ unsigned long long s_warp[2][8];

    const int tid  = threadIdx.x;
    const int lane = tid & 31;
    const int wid  = tid >> 5;
    const int base = wid * 512 + lane * 4;   // global idx of e=0

    float    m[16];
    unsigned msent[16];
#pragma unroll
    for (int e = 0; e < 16; e++) { m[e] = finf(); msent[e] = 0u; }
    if (tid == 0) { m[0] = -1.0f; msent[0] = 0xFFFFFFFFu; }  // vertex 0 in tree

    unsigned Kv = 0x7f800000u;        // cached warp key: +inf (never wins)
    unsigned Ki = (unsigned)base;
    bool     rebuild = false;

    int      j   = 0;
    int      par = 0;
    unsigned prev_death = 0;          // death of previous step (deferred STG)

    for (int step = 0; step < N - 1; step++) {
        // ---- 1. issue row loads first; everything below top hides under them
        const float4* rp = (const float4*)(g_D + ((size_t)j << 12)) + wid * 128 + lane;
        float4 q0 = __ldcg(rp);
        float4 q1 = __ldcg(rp + 32);
        float4 q2 = __ldcg(rp + 64);
        float4 q3 = __ldcg(rp + 96);

        // ---- 2. deferred output write for the previous step
        if (step > 0 && tid == 0)
            *(float2*)(out + 2 * (step - 1)) =
                make_float2(0.0f, __uint_as_float(prev_death));

        // ---- 3. rebuild cached key if our warp's cached vertex joined the
        //         tree last step (warp-uniform branch; under the load stall)
        if (rebuild) {
            unsigned u[16];
#pragma unroll
            for (int e = 0; e < 16; e++) u[e] = __float_as_uint(m[e]); // -1.0 sorts last
            unsigned rv[8], ri[8];
#pragma unroll
            for (int k = 0; k < 8; k++) {
                bool p = u[2 * k + 1] < u[2 * k];
                rv[k] = p ? u[2 * k + 1] : u[2 * k];
                ri[k] = p ? (unsigned)(2 * k + 1) : (unsigned)(2 * k);
            }
#pragma unroll
            for (int k = 0; k < 4; k++) {
                bool p = rv[2 * k + 1] < rv[2 * k];
                rv[k] = p ? rv[2 * k + 1] : rv[2 * k];
                ri[k] = p ? ri[2 * k + 1] : ri[2 * k];
            }
#pragma unroll
            for (int k = 0; k < 2; k++) {
                bool p = rv[2 * k + 1] < rv[2 * k];
                rv[k] = p ? rv[2 * k + 1] : rv[2 * k];
                ri[k] = p ? ri[2 * k + 1] : ri[2 * k];
            }
            bool p0 = rv[1] < rv[0];
            unsigned lv = p0 ? rv[1] : rv[0];
            unsigned le = p0 ? ri[1] : ri[0];
            unsigned li = (unsigned)(base + ((le >> 2) << 7) + (le & 3));
            // warp argmin of the slice (value, then first index)
            Kv = __reduce_min_sync(0xffffffffu, lv);
            unsigned c = (lv == Kv) ? li : 0xffffffffu;
            Ki = __reduce_min_sync(0xffffffffu, c);
            rebuild = false;
        }

        float dv[16] = {q0.x, q0.y, q0.z, q0.w, q1.x, q1.y, q1.z, q1.w,
                        q2.x, q2.y, q2.z, q2.w, q3.x, q3.y, q3.z, q3.w};

        // ---- 4. critical: mask row (alu pipe) + merge mind (fma pipe,
        //         off-path, interleaves freely with the tree below)
        unsigned v[16];
#pragma unroll
        for (int e = 0; e < 16; e++) v[e] = __float_as_uint(dv[e]) | msent[e];
#pragma unroll
        for (int e = 0; e < 16; e++) m[e] = fminf(m[e], dv[e]);

        // ---- 5. row argmin tree (strict < keeps earlier index)
        unsigned bv[8]; int be[8];
#pragma unroll
        for (int k = 0; k < 8; k++) {
            bool p = v[2 * k + 1] < v[2 * k];
            bv[k] = p ? v[2 * k + 1] : v[2 * k];
            be[k] = p ? (2 * k + 1) : (2 * k);
        }
#pragma unroll
        for (int k = 0; k < 4; k++) {
            bool p = bv[2 * k + 1] < bv[2 * k];
            bv[k] = p ? bv[2 * k + 1] : bv[2 * k];
            be[k] = p ? be[2 * k + 1] : be[2 * k];
        }
#pragma unroll
        for (int k = 0; k < 2; k++) {
            bool p = bv[2 * k + 1] < bv[2 * k];
            bv[k] = p ? bv[2 * k + 1] : bv[2 * k];
            be[k] = p ? be[2 * k + 1] : be[2 * k];
        }
        bool p0 = bv[1] < bv[0];
        unsigned myv = p0 ? bv[1] : bv[0];
        int      e0  = p0 ? be[1] : be[0];
        unsigned myi = (unsigned)(base + ((e0 >> 2) << 7) + (e0 & 3));

        // pre-min with the replicated cached key (exact packed-key order)
        bool tk = (Kv < myv) || (Kv == myv && Ki < myi);
        myv = tk ? Kv : myv;
        myi = tk ? Ki : myi;

        // ---- 6. stage 1: warp argmin via two REDUX ops
        unsigned wmin = __reduce_min_sync(0xffffffffu, myv);
        unsigned cand = (myv == wmin) ? myi : 0xffffffffu;
        unsigned widx = __reduce_min_sync(0xffffffffu, cand);
        if (lane == 0)
            s_warp[par][wid] = ((unsigned long long)wmin << 32) | widx;
        __syncthreads();

        // ---- 7. stage 2: every warp redundantly reduces the 8 per-warp keys
        unsigned long long k8 =
            (lane < 8) ? s_warp[par][lane] : 0xffffffffffffffffull;
        unsigned kv   = (unsigned)(k8 >> 32);
        unsigned gmin = __reduce_min_sync(0xffffffffu, kv);
        unsigned c2   = (kv == gmin) ? (unsigned)k8 : 0xffffffffu;
        unsigned gi   = __reduce_min_sync(0xffffffffu, c2);

        // ---- 8. bookkeeping (next LDG needs only j; STG deferred to top)
        j = (int)gi;
        prev_death = gmin;

        // cache update: K' = min(K, rowmin) == this warp's REDUX result
        Kv = wmin; Ki = widx;
        if (Ki == gi) rebuild = true;   // warp-uniform: winner came from us

        int own = (int)(((gi >> 9) << 5) | ((gi >> 2) & 31));
        if (own == tid) {
            int e = (int)(((gi >> 5) & 0xCu) | (gi & 3u));
            m[e] = -1.0f;               // sentinel (survives fminf)
            msent[e] = 0xFFFFFFFFu;     // row mask
        }
        par ^= 1;
    }

    // final deferred output
    if (tid == 0)
        *(float2*)(out + 2 * (N - 2)) =
            make_float2(0.0f, __uint_as_float(prev_death));
}

// ---------------------------------------------------------------------------
extern "C" void kernel_launch(void* const* d_in, const int* in_sizes, int n_in,
                              void* d_out, int out_size) {
    const float* x   = (const float*)d_in[0];
    float*       out = (float*)d_out;

    sq_kernel<<<(N + 255) / 256, 256>>>(x);
    dim3 grid(N / 64, N / 64);
    dist_kernel<<<grid, 256>>>(x);
    prim_kernel<<<1, 256>>>(out);
}

// round 11
// speedup vs baseline: 1.0602x; 1.0602x over previous
#include <cuda_runtime.h>
#include <cuda_bf16.h>
#include <cstdint>

#define N 4096
#define DF 64

// Scratch (allocation-free rule: __device__ globals)
__device__ float g_D[(size_t)N * N];   // 64 MB distance matrix, diagonal = +inf
__device__ float g_sq[N];              // squared norms

__device__ __forceinline__ float finf() { return __int_as_float(0x7f800000); }

// ---------------------------------------------------------------------------
// Kernel 0: squared norms
// ---------------------------------------------------------------------------
__global__ void sq_kernel(const float* __restrict__ x) {
    int i = blockIdx.x * blockDim.x + threadIdx.x;
    if (i >= N) return;
    const float4* xi = (const float4*)(x + (size_t)i * DF);
    float s = 0.f;
#pragma unroll
    for (int k = 0; k < DF / 4; k++) {
        float4 v = xi[k];
        s += v.x * v.x + v.y * v.y + v.z * v.z + v.w * v.w;
    }
    g_sq[i] = s;
}

// ---------------------------------------------------------------------------
// Kernel 1: distance matrix, 64x64 tiles, 256 threads, 4x4 per thread.
// ---------------------------------------------------------------------------
__global__ __launch_bounds__(256) void dist_kernel(const float* __restrict__ x) {
    __shared__ __align__(16) float sA[DF * 68];
    __shared__ __align__(16) float sB[DF * 68];

    const int t    = threadIdx.x;
    const int lrow = t >> 2;      // 0..63
    const int q    = t & 3;       // 0..3
    const int i0   = blockIdx.y * 64;
    const int j0   = blockIdx.x * 64;

    {
        const float4* xa = (const float4*)(x + (size_t)(i0 + lrow) * DF) + q * 4;
        const float4* xb = (const float4*)(x + (size_t)(j0 + lrow) * DF) + q * 4;
#pragma unroll
        for (int u = 0; u < 4; u++) {
            float4 va = xa[u];
            float4 vb = xb[u];
            int k0 = q * 16 + u * 4;
            sA[(k0 + 0) * 68 + lrow] = va.x;
            sA[(k0 + 1) * 68 + lrow] = va.y;
            sA[(k0 + 2) * 68 + lrow] = va.z;
            sA[(k0 + 3) * 68 + lrow] = va.w;
            sB[(k0 + 0) * 68 + lrow] = vb.x;
            sB[(k0 + 1) * 68 + lrow] = vb.y;
            sB[(k0 + 2) * 68 + lrow] = vb.z;
            sB[(k0 + 3) * 68 + lrow] = vb.w;
        }
    }
    __syncthreads();

    const int tx = t & 15;
    const int ty = t >> 4;

    float acc[4][4];
#pragma unroll
    for (int r = 0; r < 4; r++)
#pragma unroll
        for (int c = 0; c < 4; c++) acc[r][c] = 0.f;

#pragma unroll 8
    for (int k = 0; k < DF; k++) {
        float4 a = *(const float4*)&sA[k * 68 + ty * 4];
        float4 b = *(const float4*)&sB[k * 68 + tx * 4];
        float av[4] = {a.x, a.y, a.z, a.w};
        float bv[4] = {b.x, b.y, b.z, b.w};
#pragma unroll
        for (int r = 0; r < 4; r++)
#pragma unroll
            for (int c = 0; c < 4; c++) acc[r][c] = fmaf(av[r], bv[c], acc[r][c]);
    }

    float sqI[4], sqJ[4];
#pragma unroll
    for (int r = 0; r < 4; r++) sqI[r] = g_sq[i0 + ty * 4 + r];
#pragma unroll
    for (int c = 0; c < 4; c++) sqJ[c] = g_sq[j0 + tx * 4 + c];

#pragma unroll
    for (int r = 0; r < 4; r++) {
        int gi = i0 + ty * 4 + r;
        float4 o;
        float ov[4];
#pragma unroll
        for (int c = 0; c < 4; c++) {
            int gj = j0 + tx * 4 + c;
            float d2 = sqI[r] + sqJ[c] - 2.f * acc[r][c];
            float d  = sqrtf(fmaxf(d2, 1e-12f));
            ov[c] = (gi == gj) ? finf() : d;
        }
        o.x = ov[0]; o.y = ov[1]; o.z = ov[2]; o.w = ov[3];
        *(float4*)(g_D + (size_t)gi * N + j0 + tx * 4) = o;
    }
}

// ---------------------------------------------------------------------------
// Kernel 2: Prim scan — R5 exact selection core (256 threads, 8 warps,
// 16 elems/thread in registers, sentinel -1.0f sorts after +inf under
// unsigned compare, two REDUX per stage => bit-exact jnp.argmin semantics),
// with BARRIER-FREE cross-warp sync:
//
//  - lane0 of each warp publishes its 64-bit key via one STS.64:
//        key = value_bits<<32 | tag<<31 | idx      (idx: bits 0..11)
//    tag = (step>>1)&1 distinguishes reuses of the double-buffered slot;
//    identical across all keys of a step => unsigned-min order unaffected.
//  - every lane volatile-polls slot (lane&7) until its tag matches, then
//    an exact two-REDUX stage-2 runs redundantly in all warps.
//  - safety: a warp reaches step s+2 (overwriting buffer p) only after
//    passing the step-s+1 poll, which requires every warp to have written
//    step s+1, which happens after their step-s read. No barrier needed.
//  - output STG deferred one step (exact value rides in the key's high word).
// ---------------------------------------------------------------------------
__global__ __launch_bounds__(256, 1) void prim_kernel(float* __restrict__ out) {
    __shared__ unsigned long long s_slot[2][8];

    const int tid  = threadIdx.x;
    const int lane = tid & 31;
    const int wid  = tid >> 5;
    const int base = wid * 512 + lane * 4;   // global idx of e=0

    float m[16];
#pragma unroll
    for (int e = 0; e < 16; e++) m[e] = finf();
    if (tid == 0) m[0] = -1.0f;   // vertex 0 starts in the tree

    // init slots with tag=1 so the first-step polls (want tag=0) must wait
    // for fresh writes
    if (tid < 16)
        s_slot[tid >> 3][tid & 7] = 0x80000000ull;   // tag bit set, value 0
    __syncthreads();

    int      j          = 0;
    unsigned prev_death = 0;

    for (int step = 0; step < N - 1; step++) {
        const int      par  = step & 1;
        const unsigned want = (unsigned)((step >> 1) & 1);

        // ---- 1. row loads first (MLP=4); everything below overlaps them
        const float4* rp = (const float4*)(g_D + ((size_t)j << 12)) + wid * 128 + lane;
        float4 q0 = __ldcg(rp);
        float4 q1 = __ldcg(rp + 32);
        float4 q2 = __ldcg(rp + 64);
        float4 q3 = __ldcg(rp + 96);

        // ---- 2. deferred output for the previous step (off-path)
        if (step > 0 && tid == 0)
            *(float2*)(out + 2 * (step - 1)) =
                make_float2(0.0f, __uint_as_float(prev_death));

        float dv[16] = {q0.x, q0.y, q0.z, q0.w, q1.x, q1.y, q1.z, q1.w,
                        q2.x, q2.y, q2.z, q2.w, q3.x, q3.y, q3.z, q3.w};

        // ---- 3. merge + implicit mask (sentinel bits sort after +inf)
        unsigned v[16];
#pragma unroll
        for (int e = 0; e < 16; e++) {
            m[e] = fminf(m[e], dv[e]);
            v[e] = __float_as_uint(m[e]);
        }

        // ---- 4. local argmin tree (strict < keeps earlier index)
        unsigned bv[8]; int be[8];
#pragma unroll
        for (int k = 0; k < 8; k++) {
            bool p = v[2 * k + 1] < v[2 * k];
            bv[k] = p ? v[2 * k + 1] : v[2 * k];
            be[k] = p ? (2 * k + 1) : (2 * k);
        }
#pragma unroll
        for (int k = 0; k < 4; k++) {
            bool p = bv[2 * k + 1] < bv[2 * k];
            bv[k] = p ? bv[2 * k + 1] : bv[2 * k];
            be[k] = p ? be[2 * k + 1] : be[2 * k];
        }
#pragma unroll
        for (int k = 0; k < 2; k++) {
            bool p = bv[2 * k + 1] < bv[2 * k];
            bv[k] = p ? bv[2 * k + 1] : bv[2 * k];
            be[k] = p ? be[2 * k + 1] : be[2 * k];
        }
        bool p0 = bv[1] < bv[0];
        unsigned myv = p0 ? bv[1] : bv[0];
        int      e0  = p0 ? be[1] : be[0];
        unsigned myi = (unsigned)(base + ((e0 >> 2) << 7) + (e0 & 3));

        // ---- 5. stage 1: warp argmin via two REDUX ops (exact)
        unsigned wmin = __reduce_min_sync(0xffffffffu, myv);
        unsigned cand = (myv == wmin) ? myi : 0xffffffffu;
        unsigned widx = __reduce_min_sync(0xffffffffu, cand);

        // ---- 6. publish: one STS.64 per warp, tag embedded at bit 31
        if (lane == 0)
            s_slot[par][wid] = ((unsigned long long)wmin << 32)
                             | ((unsigned long long)want << 31) | widx;

        // ---- 7. spin-wait: each lane polls slot (lane&7) until tag matches
        const volatile unsigned long long* sl = s_slot[par];
        unsigned long long k8;
        for (;;) {
            k8 = sl[lane & 7];
            unsigned rdy = ((unsigned)(k8 >> 31) & 1u) == want;
            if (__ballot_sync(0xffffffffu, rdy) == 0xffffffffu) break;
        }

        // ---- 8. stage 2: exact two-REDUX over the 8 keys (all warps)
        unsigned kv   = (unsigned)(k8 >> 32);
        unsigned gmin = __reduce_min_sync(0xffffffffu, kv);
        unsigned c2   = (kv == gmin) ? (unsigned)k8 : 0xffffffffu;
        unsigned gidx = __reduce_min_sync(0xffffffffu, c2);
        unsigned gi   = gidx & 0xFFFu;   // strip tag bit; idx is 12 bits

        // ---- 9. bookkeeping (next LDG needs only j)
        j          = (int)gi;
        prev_death = gmin;

        int own = (int)(((gi >> 9) << 5) | ((gi >> 2) & 31));
        if (own == tid) {
            int e = (int)(((gi >> 5) & 0xCu) | (gi & 3u));
            m[e] = -1.0f;   // sentinel (survives fminf, sorts last)
        }
    }

    // final deferred output
    if (tid == 0)
        *(float2*)(out + 2 * (N - 2)) =
            make_float2(0.0f, __uint_as_float(prev_death));
}

// ---------------------------------------------------------------------------
extern "C" void kernel_launch(void* const* d_in, const int* in_sizes, int n_in,
                              void* d_out, int out_size) {
    const float* x   = (const float*)d_in[0];
    float*       out = (float*)d_out;

    sq_kernel<<<(N + 255) / 256, 256>>>(x);
    dim3 grid(N / 64, N / 64);
    dist_kernel<<<grid, 256>>>(x);
    prim_kernel<<<1, 256>>>(out);
}